// round 14
// baseline (speedup 1.0000x reference)
#include <cuda_runtime.h>
#include <math.h>
#include <cstdint>

// Problem constants
#define HD   96
#define WD   96
// tile
#define PXB  12     // pixels (w) per block
#define ROWS 4      // output rows per block
#define XW   20     // halo window cols [w0-4, w0+16), 4-aligned
#define CHS  161    // channel stride in floats: 8*20+1 (odd -> conflict-free lane stride)
#define NTHR 768

// shared layout (floats)
#define IN_SH_F   (128*CHS)          // 20608
#define CB_F      (PXB*32*36)        // 13824 per buffer : conv[p][o*8+j][z]
#define WC_SH_F   800                // [o][ky][kx][j]
#define MP_SH_F   512                // [o][t][bb][k]
#define MA_PAD    16
#define MA_SH_F   512
#define MB_SH_F   128
#define SMEM_F (IN_SH_F + 2*CB_F + WC_SH_F + MP_SH_F + MA_PAD + MA_SH_F + MB_SH_F)

// prep scratch: [0:512) mp normalized+relayout, [512:1024) ma relayout, [1024:1152) mb
__device__ float g_prep[1152];

// Blackwell packed fp32 ops (b64 register pairs)
#define FMA_F32X2(d, a, b, c) \
    asm("fma.rn.f32x2 %0, %1, %2, %3;" : "=l"(d) : "l"(a), "l"(b), "l"(c))
#define PACK_DUP_F32X2(d, v) \
    asm("mov.b64 %0, {%1, %1};" : "=l"(d) : "f"(v))
#define UNPACK_F32X2(lo, hi, in) \
    asm("mov.b64 {%0, %1}, %2;" : "=f"(lo), "=f"(hi) : "l"(in))
// group-scoped barrier: 4-warp (128-thread) named barrier
#define GROUP_BAR(id) \
    asm volatile("bar.sync %0, 128;" :: "r"(id) : "memory")

__global__ void prep_kernel(const float* __restrict__ Wp,
                            const float* __restrict__ Wa,
                            const float* __restrict__ ba)
{
    int tid = threadIdx.x;
    {
        int q8 = tid >> 4;           // o*8 + t
        int bb = (tid >> 2) & 3;
        int k  = tid & 3;
        int o  = q8 >> 3, t = q8 & 7;
        int src = o*128 + t*16 + k*4 + bb;
        float s = 0.f;
        #pragma unroll
        for (int kk = 0; kk < 4; kk++) {
            float v = Wp[o*128 + t*16 + kk*4 + bb];
            s += v * v;
        }
        float nrm = sqrtf(fmaxf(s, 1e-12f));
        g_prep[tid]       = Wp[src] / nrm;
        g_prep[512 + tid] = Wa[src];
    }
    if (tid < 128) {
        int bb = tid & 3, t = (tid >> 2) & 7, o = tid >> 5;
        float sm = 0.f;
        #pragma unroll
        for (int k = 0; k < 4; k++) sm += Wa[o*128 + t*16 + k*4 + bb];
        g_prep[1024 + tid] = ba[o*8 + t] * sm;
    }
}

// depthwise 5x5 conv for one output row: 2 pixels x 8 filters, packed f32x2
__device__ __forceinline__ void conv_compute(const float* __restrict__ ib,
                                             const float* __restrict__ wcb,
                                             int hr, int p0, uint64_t* acc2)
{
    #pragma unroll
    for (int q = 0; q < 8; q++) acc2[q] = 0ull;
    #pragma unroll
    for (int ky = 0; ky < 5; ky++) {
        float r[6];
        #pragma unroll
        for (int q = 0; q < 6; q++) r[q] = ib[(hr + ky)*XW + p0 + 2 + q];
        #pragma unroll
        for (int kx = 0; kx < 5; kx++) {
            const ulonglong2 wA = *reinterpret_cast<const ulonglong2*>(wcb + (ky*5 + kx)*8);
            const ulonglong2 wB = *reinterpret_cast<const ulonglong2*>(wcb + (ky*5 + kx)*8 + 4);
            uint64_t va2, vb2;
            PACK_DUP_F32X2(va2, r[kx]);
            PACK_DUP_F32X2(vb2, r[kx + 1]);
            FMA_F32X2(acc2[0], va2, wA.x, acc2[0]);
            FMA_F32X2(acc2[1], va2, wA.y, acc2[1]);
            FMA_F32X2(acc2[2], va2, wB.x, acc2[2]);
            FMA_F32X2(acc2[3], va2, wB.y, acc2[3]);
            FMA_F32X2(acc2[4], vb2, wA.x, acc2[4]);
            FMA_F32X2(acc2[5], vb2, wA.y, acc2[5]);
            FMA_F32X2(acc2[6], vb2, wB.x, acc2[6]);
            FMA_F32X2(acc2[7], vb2, wB.y, acc2[7]);
        }
    }
}

__device__ __forceinline__ void conv_store(float* __restrict__ buf,
                                           int p0, int o_c, int lane,
                                           const uint64_t* acc2)
{
    float* c0 = buf + p0*1152 + (o_c*8)*36 + lane;
    float* c1 = c0 + 1152;
    #pragma unroll
    for (int jp = 0; jp < 4; jp++) {
        float lo, hi;
        UNPACK_F32X2(lo, hi, acc2[jp]);
        c0[(2*jp)*36]     = lo;
        c0[(2*jp + 1)*36] = hi;
    }
    #pragma unroll
    for (int jp = 0; jp < 4; jp++) {
        float lo, hi;
        UNPACK_F32X2(lo, hi, acc2[4 + jp]);
        c1[(2*jp)*36]     = lo;
        c1[(2*jp + 1)*36] = hi;
    }
}

__global__ void __launch_bounds__(NTHR, 1)
caps2d_fused_kernel(const float* __restrict__ inp,
                    const float* __restrict__ Wc,
                    float* __restrict__ out)
{
    extern __shared__ float smem[];
    float* in_sh = smem;
    float* buf0  = in_sh + IN_SH_F;
    float* buf1  = buf0 + CB_F;
    float* wc_sh = buf1 + CB_F;
    float* mp_sh = wc_sh + WC_SH_F;
    float* ma_sh = mp_sh + MP_SH_F + MA_PAD;
    float* mb_sh = ma_sh + MA_SH_F;

    const int tid  = threadIdx.x;
    const int warp = tid >> 5;
    const int lane = tid & 31;
    const int w0   = blockIdx.x * PXB;
    const int hh0  = blockIdx.y * ROWS;
    const int n    = blockIdx.z;

    // ---- load conv weights + prepped matrices ----
    for (int e = tid; e < 800; e += NTHR) wc_sh[e] = Wc[e];
    if (tid < 512) {
        mp_sh[tid] = g_prep[tid];
        ma_sh[tid] = g_prep[512 + tid];
    }
    if (tid < 128) mb_sh[tid] = g_prep[1024 + tid];

    // ---- vector halo load: 8 rows x 20 cols x 128 ch (5 float4 groups/row) ----
    for (int e = tid; e < 128*40; e += NTHR) {
        int ch = e / 40;
        int r  = e - ch*40;
        int y  = r / 5;
        int g  = r - y*5;
        int gy  = hh0 - 2 + y;
        int gx0 = w0 - 4 + g*4;
        bool ok = (gy >= 0) && (gy < HD) && (gx0 >= 0) && (gx0 + 3 < WD);
        float4 v = make_float4(0.f, 0.f, 0.f, 0.f);
        if (ok) v = *reinterpret_cast<const float4*>(inp + ((n*128 + ch)*HD + gy)*WD + gx0);
        float* dst = in_sh + ch*CHS + y*XW + g*4;
        dst[0] = v.x; dst[1] = v.y; dst[2] = v.z; dst[3] = v.w;
    }
    __syncthreads();

    // routing-role constants
    const int half = warp & 1;
    const int p    = warp >> 1;          // 0..11
    const int gw   = w0 + p;
    const int a_   = (lane >> 2) & 3;
    const int bb   = lane & 3;
    const bool app = (lane >> 4) != 0;
    const float cx = (float)gw * (1.f/96.f);
    // conv-role constants
    const int o_c  = warp & 3;
    const int p0   = (warp >> 2) * 2;    // 0,2,..,10
    const int barid = 1 + (warp >> 2);   // 1..6
    const float* ib  = in_sh + (o_c*32 + lane)*CHS;
    const float* wcb = wc_sh + o_c*200;
    const unsigned FULL = 0xffffffffu;
    const bool x0 = (lane & 1) != 0;
    const bool x1 = (lane & 2) != 0;
    const bool x2 = (lane & 4) != 0;
    const bool x3 = (lane & 8) != 0;
    const int l0 = lane & 1;
    const int l1 = (lane >> 1) & 1;

    float vr[16];   // routing outputs, 4 per row, held to the epilogue

    // ---- prologue: conv row 0 into buf0 ----
    {
        uint64_t acc2[8];
        conv_compute(ib, wcb, 0, p0, acc2);
        conv_store(buf0, p0, o_c, lane, acc2);
    }
    GROUP_BAR(barid);

    #pragma unroll
    for (int hr = 0; hr < ROWS; hr++) {
        const float* rb = (hr & 1) ? buf1 : buf0;
        float*       wb = (hr & 1) ? buf0 : buf1;

        // ---- phase 2: u_hat[z=lane][q = o*4+tt] from rb ----
        const float cy = (float)(hh0 + hr) * (1.f/96.f);
        const float* csh = rb + p * 1152;
        float uh[16];
        #pragma unroll
        for (int o = 0; o < 4; o++) {
            #pragma unroll
            for (int tt = 0; tt < 4; tt++) {
                const int t  = half*4 + tt;
                const int j  = (app ? 4 : 0) + (t >> 1);
                const int zb = ((t & 1) << 4) + (a_ << 2);
                const float4 cv = *reinterpret_cast<const float4*>(csh + (o*8 + j)*36 + zb);
                const float* msrc = (app ? ma_sh : mp_sh) + ((o*8 + t)*4 + bb)*4;
                float4 m = *reinterpret_cast<const float4*>(msrc);
                float s0 = 0.f;
                if (app) {
                    s0 = mb_sh[(o*8 + t)*4 + bb];
                } else {
                    if (bb == 0)      m.w += cx;
                    else if (bb == 1) m.w += cy;
                }
                float s;
                s = fmaf(cv.x, m.x, s0);
                s = fmaf(cv.y, m.y, s);
                s = fmaf(cv.z, m.z, s);
                s = fmaf(cv.w, m.w, s);
                uh[o*4 + tt] = s;
            }
        }

        // ---- overlapped: conv of next row (independent stream, fills routing latency) ----
        uint64_t acc2[8];
        if (hr < ROWS - 1)
            conv_compute(ib, wcb, hr + 1, p0, acc2);

        // ---- phase 3: dynamic routing -> vr[hr*4 + tt] ----
        float* v_ = vr + hr*4;
        float bq = 0.f;
        for (int iter = 0; iter < 3; iter++) {
            float pt[4];
            if (iter == 0) {
                #pragma unroll
                for (int tt = 0; tt < 4; tt++)
                    pt[tt] = 0.5f * (uh[tt] + uh[4 + tt] + uh[8 + tt] + uh[12 + tt]);
            } else {
                float rq = 1.f / (1.f + __expf(-bq));
                #pragma unroll
                for (int tt = 0; tt < 4; tt++) {
                    float s = 0.f;
                    #pragma unroll
                    for (int o = 0; o < 4; o++) {
                        float r = __shfl_sync(FULL, rq, (lane & 16) | (o*4 + tt));
                        s = fmaf(uh[o*4 + tt], r, s);
                    }
                    pt[tt] = s;
                }
            }
            // ---- segmented norms, merge-route butterfly: 8 shfl for all 4 tt ----
            {
                float xv[4];
                #pragma unroll
                for (int tt = 0; tt < 4; tt++)
                    xv[tt] = app ? pt[tt]*pt[tt] : fabsf(pt[tt]);
                float ka = xv[l0],      sa = xv[l0 ^ 1];
                float kb = xv[2 + l0],  sb = xv[2 + (l0 ^ 1)];
                float ra = __shfl_xor_sync(FULL, sa, 1);
                float rb2 = __shfl_xor_sync(FULL, sb, 1);
                float ya = app ? (ka + ra)  : fmaxf(ka, ra);
                float yb = app ? (kb + rb2) : fmaxf(kb, rb2);
                float kc = l1 ? yb : ya;
                float sc = l1 ? ya : yb;
                float rc = __shfl_xor_sync(FULL, sc, 2);
                float z  = app ? (kc + rc) : fmaxf(kc, rc);
                float z4 = __shfl_xor_sync(FULL, z, 4);
                z = app ? (z + z4) : fmaxf(z, z4);
                float z8 = __shfl_xor_sync(FULL, z, 8);
                z = app ? (z + z8) : fmaxf(z, z8);            // z = S[lane&3]
                float w  = __shfl_xor_sync(FULL, z, 1);
                float sE = l0 ? w : z;
                float sO = l0 ? z : w;
                float rE = __shfl_xor_sync(FULL, sE, 2);
                float rO = __shfl_xor_sync(FULL, sO, 2);
                float S[4];
                S[0] = l1 ? rE : sE;
                S[1] = l1 ? rO : sO;
                S[2] = l1 ? sE : rE;
                S[3] = l1 ? sO : rO;
                #pragma unroll
                for (int tt = 0; tt < 4; tt++) {
                    if (app) {
                        float x = S[tt];
                        v_[tt] = x / (1.f + x) * pt[tt] * rsqrtf(x + 1e-9f);
                    } else {
                        v_[tt] = pt[tt] / S[tt];
                    }
                }
            }
            if (iter == 2) break;

            // multi-value butterfly, 15+1 shfl
            float t8[8];
            #pragma unroll
            for (int j = 0; j < 8; j++) {
                float sa = uh[2*j]     * v_[(2*j)     & 3];
                float sb = uh[2*j + 1] * v_[(2*j + 1) & 3];
                float keep = x0 ? sb : sa;
                float send = x0 ? sa : sb;
                t8[j] = keep + __shfl_xor_sync(FULL, send, 1);
            }
            float t4[4];
            #pragma unroll
            for (int j = 0; j < 4; j++) {
                float keep = x1 ? t8[2*j + 1] : t8[2*j];
                float send = x1 ? t8[2*j]     : t8[2*j + 1];
                t4[j] = keep + __shfl_xor_sync(FULL, send, 2);
            }
            float t2[2];
            #pragma unroll
            for (int j = 0; j < 2; j++) {
                float keep = x2 ? t4[2*j + 1] : t4[2*j];
                float send = x2 ? t4[2*j]     : t4[2*j + 1];
                t2[j] = keep + __shfl_xor_sync(FULL, send, 4);
            }
            {
                float keep = x3 ? t2[1] : t2[0];
                float send = x3 ? t2[0] : t2[1];
                float R = keep + __shfl_xor_sync(FULL, send, 8);
                float other = __shfl_xor_sync(FULL, R, 16);
                bq = fmaf(R, other, bq);
            }
        }

        // ---- publish next row's conv into the other buffer ----
        if (hr < ROWS - 1)
            conv_store(wb, p0, o_c, lane, acc2);
        GROUP_BAR(barid);   // conv(hr+1) visible; all reads of rb complete
    }

    __syncthreads();   // realign all groups before buffers are repurposed

    // ---- epilogue: stage all rows, buf0 reused as os[row][hr*12+p], stride 49 ----
    #pragma unroll
    for (int hr = 0; hr < ROWS; hr++)
        #pragma unroll
        for (int tt = 0; tt < 4; tt++)
            buf0[((half*4 + tt)*32 + lane)*49 + hr*PXB + p] = vr[hr*4 + tt];
    __syncthreads();

    // ---- coalesced writeout ----
    for (int e = tid; e < 256*48; e += NTHR) {
        int row = e / 48;
        int c   = e - row*48;
        int hw  = c / PXB;
        int x   = c - hw*PXB;
        out[(n*256 + row)*(HD*WD) + (hh0 + hw)*WD + w0 + x] = buf0[row*49 + c];
    }
}

extern "C" void kernel_launch(void* const* d_in, const int* in_sizes, int n_in,
                              void* d_out, int out_size)
{
    const float* inp = (const float*)d_in[0];   // (4,4,32,96,96)
    const float* Wc  = (const float*)d_in[1];   // (4,5,5,1,8)
    const float* Wp  = (const float*)d_in[2];   // (4,16,8)
    const float* Wa  = (const float*)d_in[3];   // (4,16,8)
    const float* ba  = (const float*)d_in[4];   // (4,8)
    float* out = (float*)d_out;                 // (4,8,32,96,96)

    // weight prep (normalization/relayout/bias-fold) once
    prep_kernel<<<1, 512>>>(Wp, Wa, ba);

    const int smem_bytes = SMEM_F * (int)sizeof(float);
    cudaFuncSetAttribute(caps2d_fused_kernel,
                         cudaFuncAttributeMaxDynamicSharedMemorySize, smem_bytes);

    dim3 grid(WD / PXB, HD / ROWS, 4);   // (8, 24, 4)
    dim3 block(NTHR);
    caps2d_fused_kernel<<<grid, block, smem_bytes>>>(inp, Wc, out);
}

// round 15
// speedup vs baseline: 1.1718x; 1.1718x over previous
#include <cuda_runtime.h>
#include <math.h>
#include <cstdint>

// Problem constants
#define HD   96
#define WD   96
// tile
#define PXB  16     // pixels (w) per block
#define ROWS 4      // output rows per block
#define XW   24     // halo window cols [w0-4, w0+20), 4-aligned
#define CHS  193    // channel stride in floats: 8*24+1 (odd -> conflict-free lane stride)

// shared layout (floats)
#define IN_SH_F   (128*CHS)          // 24704
#define CONV_SH_F (PXB*32*36)        // 18432 : conv[p][o*8+j][z] ; epilogue: staging 256x65
#define WC_SH_F   800                // [o][ky][kx][j]
#define MP_SH_F   512                // [o][t][bb][k]  (k contiguous -> LDS.128)
#define MA_PAD    16
#define MA_SH_F   512
#define MB_SH_F   128
#define SMEM_F (IN_SH_F + CONV_SH_F + WC_SH_F + MP_SH_F + MA_PAD + MA_SH_F + MB_SH_F)

// prep scratch: [0:512) mp normalized+relayout, [512:1024) ma relayout, [1024:1152) mb
__device__ float g_prep[1152];

// Blackwell packed fp32 ops (b64 register pairs)
#define FMA_F32X2(d, a, b, c) \
    asm("fma.rn.f32x2 %0, %1, %2, %3;" : "=l"(d) : "l"(a), "l"(b), "l"(c))
#define PACK_DUP_F32X2(d, v) \
    asm("mov.b64 %0, {%1, %1};" : "=l"(d) : "f"(v))
#define UNPACK_F32X2(lo, hi, in) \
    asm("mov.b64 {%0, %1}, %2;" : "=f"(lo), "=f"(hi) : "l"(in))
// group-scoped barrier: 4-warp (128-thread) named barrier
#define GROUP_BAR(id) \
    asm volatile("bar.sync %0, 128;" :: "r"(id) : "memory")

__global__ void prep_kernel(const float* __restrict__ Wp,
                            const float* __restrict__ Wa,
                            const float* __restrict__ ba)
{
    int tid = threadIdx.x;
    {
        int q8 = tid >> 4;           // o*8 + t
        int bb = (tid >> 2) & 3;
        int k  = tid & 3;
        int o  = q8 >> 3, t = q8 & 7;
        int src = o*128 + t*16 + k*4 + bb;
        float s = 0.f;
        #pragma unroll
        for (int kk = 0; kk < 4; kk++) {
            float v = Wp[o*128 + t*16 + kk*4 + bb];
            s += v * v;
        }
        float nrm = sqrtf(fmaxf(s, 1e-12f));
        g_prep[tid]       = Wp[src] / nrm;
        g_prep[512 + tid] = Wa[src];
    }
    if (tid < 128) {
        int bb = tid & 3, t = (tid >> 2) & 7, o = tid >> 5;
        float sm = 0.f;
        #pragma unroll
        for (int k = 0; k < 4; k++) sm += Wa[o*128 + t*16 + k*4 + bb];
        g_prep[1024 + tid] = ba[o*8 + t] * sm;
    }
}

// depthwise 5x5 conv for one output row: 2 pixels x 8 filters, packed f32x2
__device__ __forceinline__ void conv_compute(const float* __restrict__ ib,
                                             const float* __restrict__ wcb,
                                             int hr, int p0, uint64_t* acc2)
{
    #pragma unroll
    for (int q = 0; q < 8; q++) acc2[q] = 0ull;
    #pragma unroll
    for (int ky = 0; ky < 5; ky++) {
        float r[6];
        #pragma unroll
        for (int q = 0; q < 6; q++) r[q] = ib[(hr + ky)*XW + p0 + 2 + q];
        #pragma unroll
        for (int kx = 0; kx < 5; kx++) {
            const ulonglong2 wA = *reinterpret_cast<const ulonglong2*>(wcb + (ky*5 + kx)*8);
            const ulonglong2 wB = *reinterpret_cast<const ulonglong2*>(wcb + (ky*5 + kx)*8 + 4);
            uint64_t va2, vb2;
            PACK_DUP_F32X2(va2, r[kx]);
            PACK_DUP_F32X2(vb2, r[kx + 1]);
            FMA_F32X2(acc2[0], va2, wA.x, acc2[0]);
            FMA_F32X2(acc2[1], va2, wA.y, acc2[1]);
            FMA_F32X2(acc2[2], va2, wB.x, acc2[2]);
            FMA_F32X2(acc2[3], va2, wB.y, acc2[3]);
            FMA_F32X2(acc2[4], vb2, wA.x, acc2[4]);
            FMA_F32X2(acc2[5], vb2, wA.y, acc2[5]);
            FMA_F32X2(acc2[6], vb2, wB.x, acc2[6]);
            FMA_F32X2(acc2[7], vb2, wB.y, acc2[7]);
        }
    }
}

__device__ __forceinline__ void conv_store(float* __restrict__ buf,
                                           int p0, int o_c, int lane,
                                           const uint64_t* acc2)
{
    float* c0 = buf + p0*1152 + (o_c*8)*36 + lane;
    float* c1 = c0 + 1152;
    #pragma unroll
    for (int jp = 0; jp < 4; jp++) {
        float lo, hi;
        UNPACK_F32X2(lo, hi, acc2[jp]);
        c0[(2*jp)*36]     = lo;
        c0[(2*jp + 1)*36] = hi;
    }
    #pragma unroll
    for (int jp = 0; jp < 4; jp++) {
        float lo, hi;
        UNPACK_F32X2(lo, hi, acc2[4 + jp]);
        c1[(2*jp)*36]     = lo;
        c1[(2*jp + 1)*36] = hi;
    }
}

__global__ void __launch_bounds__(1024, 1)
caps2d_fused_kernel(const float* __restrict__ inp,
                    const float* __restrict__ Wc,
                    float* __restrict__ out)
{
    extern __shared__ float smem[];
    float* in_sh   = smem;
    float* conv_sh = in_sh + IN_SH_F;
    float* wc_sh   = conv_sh + CONV_SH_F;
    float* mp_sh   = wc_sh + WC_SH_F;
    float* ma_sh   = mp_sh + MP_SH_F + MA_PAD;
    float* mb_sh   = ma_sh + MA_SH_F;

    const int tid  = threadIdx.x;
    const int warp = tid >> 5;
    const int lane = tid & 31;
    const int w0   = blockIdx.x * PXB;
    const int hh0  = blockIdx.y * ROWS;
    const int n    = blockIdx.z;

    // ---- load conv weights + prepped matrices ----
    if (tid < 800) wc_sh[tid] = Wc[tid];
    if (tid < 512) {
        mp_sh[tid] = g_prep[tid];
        ma_sh[tid] = g_prep[512 + tid];
    }
    if (tid < 128) mb_sh[tid] = g_prep[1024 + tid];

    // ---- vector halo load: 8 rows x 24 cols x 128 ch ----
    {
        int id  = tid & 63;          // (y,g): 8 rows x 6 float4 groups (48 of 64 used)
        int y   = id >> 3;           // 0..7
        int g   = id & 7;            // 0..7, valid g<6
        int ch0 = tid >> 6;          // 0..15 ; ch = ch0 + 16*c
        int gy  = hh0 - 2 + y;
        int gx0 = w0 - 4 + g*4;
        bool act = (g < 6);
        bool ok  = act && (gy >= 0) && (gy < HD) && (gx0 >= 0) && (gx0 + 3 < WD);
        const float* src = inp + ((n*128 + ch0)*HD + gy)*WD + gx0;
        float* dst = in_sh + ch0*CHS + y*XW + g*4;
        #pragma unroll
        for (int c = 0; c < 8; c++) {
            float4 v = make_float4(0.f, 0.f, 0.f, 0.f);
            if (ok) v = *reinterpret_cast<const float4*>(src);
            if (act) { dst[0] = v.x; dst[1] = v.y; dst[2] = v.z; dst[3] = v.w; }
            src += 16*HD*WD;
            dst += 16*CHS;
        }
    }
    __syncthreads();

    // routing-role constants
    const int half = warp & 1;
    const int p    = warp >> 1;          // 0..15
    const int gw   = w0 + p;
    const int a_   = (lane >> 2) & 3;
    const int bb   = lane & 3;
    const bool app = (lane >> 4) != 0;
    const float cx = (float)gw * (1.f/96.f);
    // conv-role constants
    const int o_c  = warp & 3;
    const int p0   = (warp >> 2) * 2;    // 0,2,..,14
    const int barid = 1 + (warp >> 2);   // 1..8
    const float* ib  = in_sh + (o_c*32 + lane)*CHS;
    const float* wcb = wc_sh + o_c*200;
    const unsigned FULL = 0xffffffffu;
    const bool x0 = (lane & 1) != 0;
    const bool x1 = (lane & 2) != 0;
    const bool x2 = (lane & 4) != 0;
    const bool x3 = (lane & 8) != 0;
    const int l0 = lane & 1;
    const int l1 = (lane >> 1) & 1;

    float vr[16];   // routing outputs, 4 per row, held to the epilogue

    // ---- prologue: conv row 0 ----
    {
        uint64_t acc2[8];
        conv_compute(ib, wcb, 0, p0, acc2);
        conv_store(conv_sh, p0, o_c, lane, acc2);
    }
    GROUP_BAR(barid);

    #pragma unroll
    for (int hr = 0; hr < ROWS; hr++) {
        // ---- phase 2: u_hat[z=lane][q = o*4+tt] ----
        const float cy = (float)(hh0 + hr) * (1.f/96.f);
        const float* csh = conv_sh + p * 1152;
        float uh[16];
        #pragma unroll
        for (int o = 0; o < 4; o++) {
            #pragma unroll
            for (int tt = 0; tt < 4; tt++) {
                const int t  = half*4 + tt;
                const int j  = (app ? 4 : 0) + (t >> 1);
                const int zb = ((t & 1) << 4) + (a_ << 2);
                const float4 cv = *reinterpret_cast<const float4*>(csh + (o*8 + j)*36 + zb);
                const float* msrc = (app ? ma_sh : mp_sh) + ((o*8 + t)*4 + bb)*4;
                float4 m = *reinterpret_cast<const float4*>(msrc);
                float s0 = 0.f;
                if (app) {
                    s0 = mb_sh[(o*8 + t)*4 + bb];
                } else {
                    if (bb == 0)      m.w += cx;
                    else if (bb == 1) m.w += cy;
                }
                float s;
                s = fmaf(cv.x, m.x, s0);
                s = fmaf(cv.y, m.y, s);
                s = fmaf(cv.z, m.z, s);
                s = fmaf(cv.w, m.w, s);
                uh[o*4 + tt] = s;
            }
        }

        // ---- overlapped: conv(hr+1) into registers; store deferred past routing ----
        uint64_t acc2[8];
        if (hr < ROWS - 1)
            conv_compute(ib, wcb, hr + 1, p0, acc2);

        // ---- phase 3: dynamic routing -> vr[hr*4 + tt] ----
        float* v_ = vr + hr*4;
        float bq = 0.f;
        for (int iter = 0; iter < 3; iter++) {
            float pt[4];
            if (iter == 0) {
                #pragma unroll
                for (int tt = 0; tt < 4; tt++)
                    pt[tt] = 0.5f * (uh[tt] + uh[4 + tt] + uh[8 + tt] + uh[12 + tt]);
            } else {
                float rq = 1.f / (1.f + __expf(-bq));
                #pragma unroll
                for (int tt = 0; tt < 4; tt++) {
                    float s = 0.f;
                    #pragma unroll
                    for (int o = 0; o < 4; o++) {
                        float r = __shfl_sync(FULL, rq, (lane & 16) | (o*4 + tt));
                        s = fmaf(uh[o*4 + tt], r, s);
                    }
                    pt[tt] = s;
                }
            }
            // ---- segmented norms, merge-route butterfly: 8 shfl for all 4 tt ----
            {
                float xv[4];
                #pragma unroll
                for (int tt = 0; tt < 4; tt++)
                    xv[tt] = app ? pt[tt]*pt[tt] : fabsf(pt[tt]);
                float ka = xv[l0],      sa = xv[l0 ^ 1];
                float kb = xv[2 + l0],  sb = xv[2 + (l0 ^ 1)];
                float ra  = __shfl_xor_sync(FULL, sa, 1);
                float rb2 = __shfl_xor_sync(FULL, sb, 1);
                float ya = app ? (ka + ra)  : fmaxf(ka, ra);
                float yb = app ? (kb + rb2) : fmaxf(kb, rb2);
                float kc = l1 ? yb : ya;
                float sc = l1 ? ya : yb;
                float rc = __shfl_xor_sync(FULL, sc, 2);
                float z  = app ? (kc + rc) : fmaxf(kc, rc);
                float z4 = __shfl_xor_sync(FULL, z, 4);
                z = app ? (z + z4) : fmaxf(z, z4);
                float z8 = __shfl_xor_sync(FULL, z, 8);
                z = app ? (z + z8) : fmaxf(z, z8);            // z = S[lane&3]
                float w  = __shfl_xor_sync(FULL, z, 1);
                float sE = l0 ? w : z;
                float sO = l0 ? z : w;
                float rE = __shfl_xor_sync(FULL, sE, 2);
                float rO = __shfl_xor_sync(FULL, sO, 2);
                float S[4];
                S[0] = l1 ? rE : sE;
                S[1] = l1 ? rO : sO;
                S[2] = l1 ? sE : rE;
                S[3] = l1 ? sO : rO;
                #pragma unroll
                for (int tt = 0; tt < 4; tt++) {
                    if (app) {
                        float x = S[tt];
                        v_[tt] = x / (1.f + x) * pt[tt] * rsqrtf(x + 1e-9f);
                    } else {
                        v_[tt] = pt[tt] / S[tt];
                    }
                }
            }
            if (iter == 2) break;

            // multi-value butterfly, 15+1 shfl
            float t8[8];
            #pragma unroll
            for (int j = 0; j < 8; j++) {
                float sa = uh[2*j]     * v_[(2*j)     & 3];
                float sb = uh[2*j + 1] * v_[(2*j + 1) & 3];
                float keep = x0 ? sb : sa;
                float send = x0 ? sa : sb;
                t8[j] = keep + __shfl_xor_sync(FULL, send, 1);
            }
            float t4[4];
            #pragma unroll
            for (int j = 0; j < 4; j++) {
                float keep = x1 ? t8[2*j + 1] : t8[2*j];
                float send = x1 ? t8[2*j]     : t8[2*j + 1];
                t4[j] = keep + __shfl_xor_sync(FULL, send, 2);
            }
            float t2[2];
            #pragma unroll
            for (int j = 0; j < 2; j++) {
                float keep = x2 ? t4[2*j + 1] : t4[2*j];
                float send = x2 ? t4[2*j]     : t4[2*j + 1];
                t2[j] = keep + __shfl_xor_sync(FULL, send, 4);
            }
            {
                float keep = x3 ? t2[1] : t2[0];
                float send = x3 ? t2[0] : t2[1];
                float R = keep + __shfl_xor_sync(FULL, send, 8);
                float other = __shfl_xor_sync(FULL, R, 16);
                bq = fmaf(R, other, bq);
            }
        }

        GROUP_BAR(barid);   // group's conv_sh reads done
        if (hr < ROWS - 1) {
            conv_store(conv_sh, p0, o_c, lane, acc2);
            GROUP_BAR(barid);   // stores visible before next phase 2
        }
    }

    __syncthreads();   // realign all groups before conv_sh is repurposed

    // ---- epilogue: stage all 4 rows, conv_sh reused as os[row][hr*16+p], stride 65 ----
    #pragma unroll
    for (int hr = 0; hr < ROWS; hr++)
        #pragma unroll
        for (int tt = 0; tt < 4; tt++)
            conv_sh[((half*4 + tt)*32 + lane)*65 + hr*16 + p] = vr[hr*4 + tt];
    __syncthreads();

    // ---- coalesced writeout: 16 independent STG per thread ----
    {
        int x  = tid & 15;
        int hw = (tid >> 4) & 3;
        int r0 = tid >> 6;          // 0..15
        const float* os = conv_sh + hw*16 + x;
        float* ob = out + n*256*(HD*WD) + (hh0 + hw)*WD + w0 + x;
        #pragma unroll
        for (int k = 0; k < 16; k++) {
            int row = r0 + 16*k;
            ob[row*(HD*WD)] = os[row*65];
        }
    }
}

extern "C" void kernel_launch(void* const* d_in, const int* in_sizes, int n_in,
                              void* d_out, int out_size)
{
    const float* inp = (const float*)d_in[0];   // (4,4,32,96,96)
    const float* Wc  = (const float*)d_in[1];   // (4,5,5,1,8)
    const float* Wp  = (const float*)d_in[2];   // (4,16,8)
    const float* Wa  = (const float*)d_in[3];   // (4,16,8)
    const float* ba  = (const float*)d_in[4];   // (4,8)
    float* out = (float*)d_out;                 // (4,8,32,96,96)

    // weight prep (normalization/relayout/bias-fold) once
    prep_kernel<<<1, 512>>>(Wp, Wa, ba);

    const int smem_bytes = SMEM_F * (int)sizeof(float);
    cudaFuncSetAttribute(caps2d_fused_kernel,
                         cudaFuncAttributeMaxDynamicSharedMemorySize, smem_bytes);

    dim3 grid(WD / PXB, HD / ROWS, 4);   // (6, 24, 4)
    dim3 block(1024);
    caps2d_fused_kernel<<<grid, block, smem_bytes>>>(inp, Wc, out);
}

// round 16
// speedup vs baseline: 1.3267x; 1.1322x over previous
#include <cuda_runtime.h>
#include <math.h>
#include <cstdint>

// Problem constants
#define HD   96
#define WD   96
// tile
#define PXB  16     // pixels (w) per block
#define ROWS 4      // output rows per block
#define XW   24     // halo window cols [w0-4, w0+20), 4-aligned
#define CHS  193    // channel stride in floats: 8*24+1 (odd -> conflict-free lane stride)

// shared layout (floats)
#define IN_SH_F   (128*CHS)          // 24704
#define CONV_SH_F (PXB*32*36)        // 18432 : conv[p][o*8+j][z] ; epilogue: staging 256x65
#define WC_SH_F   800                // [o][ky][kx][j]
#define MP_SH_F   512                // [o][t][bb][k]  (k contiguous -> LDS.128)
#define MA_PAD    16
#define MA_SH_F   512
#define MB_SH_F   128
#define SMEM_F (IN_SH_F + CONV_SH_F + WC_SH_F + MP_SH_F + MA_PAD + MA_SH_F + MB_SH_F)

// prep scratch: [0:512) mp normalized+relayout, [512:1024) ma relayout, [1024:1152) mb
__device__ float g_prep[1152];

// Blackwell packed fp32 ops (b64 register pairs)
#define FMA_F32X2(d, a, b, c) \
    asm("fma.rn.f32x2 %0, %1, %2, %3;" : "=l"(d) : "l"(a), "l"(b), "l"(c))
#define PACK_DUP_F32X2(d, v) \
    asm("mov.b64 %0, {%1, %1};" : "=l"(d) : "f"(v))
#define UNPACK_F32X2(lo, hi, in) \
    asm("mov.b64 {%0, %1}, %2;" : "=f"(lo), "=f"(hi) : "l"(in))
// group-scoped barrier: 4-warp (128-thread) named barrier
#define GROUP_BAR(id) \
    asm volatile("bar.sync %0, 128;" :: "r"(id) : "memory")

__global__ void prep_kernel(const float* __restrict__ Wp,
                            const float* __restrict__ Wa,
                            const float* __restrict__ ba)
{
    int tid = threadIdx.x;
    {
        int q8 = tid >> 4;           // o*8 + t
        int bb = (tid >> 2) & 3;
        int k  = tid & 3;
        int o  = q8 >> 3, t = q8 & 7;
        int src = o*128 + t*16 + k*4 + bb;
        float s = 0.f;
        #pragma unroll
        for (int kk = 0; kk < 4; kk++) {
            float v = Wp[o*128 + t*16 + kk*4 + bb];
            s += v * v;
        }
        float nrm = sqrtf(fmaxf(s, 1e-12f));
        g_prep[tid]       = Wp[src] / nrm;
        g_prep[512 + tid] = Wa[src];
    }
    if (tid < 128) {
        int bb = tid & 3, t = (tid >> 2) & 7, o = tid >> 5;
        float sm = 0.f;
        #pragma unroll
        for (int k = 0; k < 4; k++) sm += Wa[o*128 + t*16 + k*4 + bb];
        g_prep[1024 + tid] = ba[o*8 + t] * sm;
    }
}

__global__ void __launch_bounds__(1024, 1)
caps2d_fused_kernel(const float* __restrict__ inp,
                    const float* __restrict__ Wc,
                    float* __restrict__ out)
{
    extern __shared__ float smem[];
    float* in_sh   = smem;
    float* conv_sh = in_sh + IN_SH_F;
    float* wc_sh   = conv_sh + CONV_SH_F;
    float* mp_sh   = wc_sh + WC_SH_F;
    float* ma_sh   = mp_sh + MP_SH_F + MA_PAD;
    float* mb_sh   = ma_sh + MA_SH_F;

    const int tid  = threadIdx.x;
    const int warp = tid >> 5;
    const int lane = tid & 31;
    const int w0   = blockIdx.x * PXB;
    const int hh0  = blockIdx.y * ROWS;
    const int n    = blockIdx.z;

    // ---- load conv weights + prepped matrices ----
    if (tid < 800) wc_sh[tid] = Wc[tid];
    if (tid < 512) {
        mp_sh[tid] = g_prep[tid];
        ma_sh[tid] = g_prep[512 + tid];
    }
    if (tid < 128) mb_sh[tid] = g_prep[1024 + tid];

    // ---- vector halo load: 8 rows x 24 cols x 128 ch ----
    {
        int id  = tid & 63;          // (y,g): 8 rows x 6 float4 groups (48 of 64 used)
        int y   = id >> 3;           // 0..7
        int g   = id & 7;            // 0..7, valid g<6
        int ch0 = tid >> 6;          // 0..15 ; ch = ch0 + 16*c
        int gy  = hh0 - 2 + y;
        int gx0 = w0 - 4 + g*4;
        bool act = (g < 6);
        bool ok  = act && (gy >= 0) && (gy < HD) && (gx0 >= 0) && (gx0 + 3 < WD);
        const float* src = inp + ((n*128 + ch0)*HD + gy)*WD + gx0;
        float* dst = in_sh + ch0*CHS + y*XW + g*4;
        #pragma unroll
        for (int c = 0; c < 8; c++) {
            float4 v = make_float4(0.f, 0.f, 0.f, 0.f);
            if (ok) v = *reinterpret_cast<const float4*>(src);
            if (act) { dst[0] = v.x; dst[1] = v.y; dst[2] = v.z; dst[3] = v.w; }
            src += 16*HD*WD;
            dst += 16*CHS;
        }
    }
    __syncthreads();

    // routing-role constants
    const int half = warp & 1;
    const int p    = warp >> 1;          // 0..15
    const int gw   = w0 + p;
    const int a_   = (lane >> 2) & 3;
    const int bb   = lane & 3;
    const bool app = (lane >> 4) != 0;
    const float cx = (float)gw * (1.f/96.f);
    // conv-role constants
    const int o_c  = warp & 3;
    const int p0   = (warp >> 2) * 2;    // 0,2,..,14
    const int barid = 1 + (warp >> 2);   // 1..8
    const unsigned FULL = 0xffffffffu;
    const bool x0 = (lane & 1) != 0;
    const bool x1 = (lane & 2) != 0;
    const bool x2 = (lane & 4) != 0;
    const bool x3 = (lane & 8) != 0;
    const int l0 = lane & 1;
    const int l1 = (lane >> 1) & 1;

    float vr[16];   // routing outputs, 4 per row, held to the epilogue

    #pragma unroll
    for (int hr = 0; hr < ROWS; hr++) {
        // ---- phase 1: depthwise 5x5 conv, packed f32x2 (j-pairs) ----
        {
            uint64_t acc2[8];        // [px(2)][jpair(4)]
            #pragma unroll
            for (int q = 0; q < 8; q++) acc2[q] = 0ull;
            const float* ib  = in_sh + (o_c*32 + lane)*CHS;
            const float* wcb = wc_sh + o_c*200;
            #pragma unroll
            for (int ky = 0; ky < 5; ky++) {
                float r[6];
                #pragma unroll
                for (int q = 0; q < 6; q++) r[q] = ib[(hr + ky)*XW + p0 + 2 + q];
                #pragma unroll
                for (int kx = 0; kx < 5; kx++) {
                    const ulonglong2 wA = *reinterpret_cast<const ulonglong2*>(wcb + (ky*5 + kx)*8);
                    const ulonglong2 wB = *reinterpret_cast<const ulonglong2*>(wcb + (ky*5 + kx)*8 + 4);
                    uint64_t va2, vb2;
                    PACK_DUP_F32X2(va2, r[kx]);
                    PACK_DUP_F32X2(vb2, r[kx + 1]);
                    FMA_F32X2(acc2[0], va2, wA.x, acc2[0]);
                    FMA_F32X2(acc2[1], va2, wA.y, acc2[1]);
                    FMA_F32X2(acc2[2], va2, wB.x, acc2[2]);
                    FMA_F32X2(acc2[3], va2, wB.y, acc2[3]);
                    FMA_F32X2(acc2[4], vb2, wA.x, acc2[4]);
                    FMA_F32X2(acc2[5], vb2, wA.y, acc2[5]);
                    FMA_F32X2(acc2[6], vb2, wB.x, acc2[6]);
                    FMA_F32X2(acc2[7], vb2, wB.y, acc2[7]);
                }
            }
            float* c0 = conv_sh + p0*(32*36)       + (o_c*8)*36 + lane;
            float* c1 = conv_sh + (p0 + 1)*(32*36) + (o_c*8)*36 + lane;
            #pragma unroll
            for (int jp = 0; jp < 4; jp++) {
                float lo, hi;
                UNPACK_F32X2(lo, hi, acc2[jp]);
                c0[(2*jp)*36]     = lo;
                c0[(2*jp + 1)*36] = hi;
            }
            #pragma unroll
            for (int jp = 0; jp < 4; jp++) {
                float lo, hi;
                UNPACK_F32X2(lo, hi, acc2[4 + jp]);
                c1[(2*jp)*36]     = lo;
                c1[(2*jp + 1)*36] = hi;
            }
        }
        GROUP_BAR(barid);   // group's conv tiles ready; role swap within group

        // ---- phase 2: u_hat[z=lane][q = o*4+tt] ----
        const float cy = (float)(hh0 + hr) * (1.f/96.f);
        // per-lane coordinate term: pos lanes add coordv*c[3], app lanes 0
        const float coordv = app ? 0.f : (bb == 0 ? cx : (bb == 1 ? cy : 0.f));
        float* csh = conv_sh + p * (32*36);
        float uh[16];
        #pragma unroll
        for (int o = 0; o < 4; o++) {
            #pragma unroll
            for (int tt = 0; tt < 4; tt++) {
                const int t  = half*4 + tt;
                const int j  = (app ? 4 : 0) + (t >> 1);
                const int zb = ((t & 1) << 4) + (a_ << 2);
                const float4 cv = *reinterpret_cast<const float4*>(csh + (o*8 + j)*36 + zb);
                const float* msrc = (app ? ma_sh : mp_sh) + ((o*8 + t)*4 + bb)*4;
                const float4 m = *reinterpret_cast<const float4*>(msrc);
                float s0 = app ? mb_sh[(o*8 + t)*4 + bb] : 0.f;
                float s;
                s = fmaf(cv.x, m.x, s0);
                s = fmaf(cv.y, m.y, s);
                s = fmaf(cv.z, m.z, s);
                s = fmaf(cv.w, m.w, s);
                s = fmaf(cv.w, coordv, s);
                uh[o*4 + tt] = s;
            }
        }

        // ---- phase 3: dynamic routing -> vr[hr*4 + tt] ----
        float* v_ = vr + hr*4;
        float bq = 0.f;
        for (int iter = 0; iter < 3; iter++) {
            float pt[4];
            if (iter == 0) {
                #pragma unroll
                for (int tt = 0; tt < 4; tt++)
                    pt[tt] = 0.5f * (uh[tt] + uh[4 + tt] + uh[8 + tt] + uh[12 + tt]);
            } else {
                float rq = __fdividef(1.f, 1.f + __expf(-bq));
                #pragma unroll
                for (int tt = 0; tt < 4; tt++) {
                    float s = 0.f;
                    #pragma unroll
                    for (int o = 0; o < 4; o++) {
                        float r = __shfl_sync(FULL, rq, (lane & 16) | (o*4 + tt));
                        s = fmaf(uh[o*4 + tt], r, s);
                    }
                    pt[tt] = s;
                }
            }
            // ---- segmented norms, merge-route butterfly: 8 shfl for all 4 tt ----
            {
                float xv[4];
                #pragma unroll
                for (int tt = 0; tt < 4; tt++)
                    xv[tt] = app ? pt[tt]*pt[tt] : fabsf(pt[tt]);
                float ka = xv[l0],      sa = xv[l0 ^ 1];
                float kb = xv[2 + l0],  sb = xv[2 + (l0 ^ 1)];
                float ra  = __shfl_xor_sync(FULL, sa, 1);
                float rb2 = __shfl_xor_sync(FULL, sb, 1);
                float ya = app ? (ka + ra)  : fmaxf(ka, ra);
                float yb = app ? (kb + rb2) : fmaxf(kb, rb2);
                float kc = l1 ? yb : ya;
                float sc = l1 ? ya : yb;
                float rc = __shfl_xor_sync(FULL, sc, 2);
                float z  = app ? (kc + rc) : fmaxf(kc, rc);
                float z4 = __shfl_xor_sync(FULL, z, 4);
                z = app ? (z + z4) : fmaxf(z, z4);
                float z8 = __shfl_xor_sync(FULL, z, 8);
                z = app ? (z + z8) : fmaxf(z, z8);            // z = S[lane&3]
                float w  = __shfl_xor_sync(FULL, z, 1);
                float sE = l0 ? w : z;
                float sO = l0 ? z : w;
                float rE = __shfl_xor_sync(FULL, sE, 2);
                float rO = __shfl_xor_sync(FULL, sO, 2);
                float S[4];
                S[0] = l1 ? rE : sE;
                S[1] = l1 ? rO : sO;
                S[2] = l1 ? sE : rE;
                S[3] = l1 ? sO : rO;
                #pragma unroll
                for (int tt = 0; tt < 4; tt++) {
                    if (app) {
                        float x = S[tt];
                        v_[tt] = __fdividef(x, 1.f + x) * pt[tt] * rsqrtf(x + 1e-9f);
                    } else {
                        v_[tt] = __fdividef(pt[tt], S[tt]);
                    }
                }
            }
            if (iter == 2) break;

            // multi-value butterfly, 15+1 shfl
            float t8[8];
            #pragma unroll
            for (int j = 0; j < 8; j++) {
                float sa = uh[2*j]     * v_[(2*j)     & 3];
                float sb = uh[2*j + 1] * v_[(2*j + 1) & 3];
                float keep = x0 ? sb : sa;
                float send = x0 ? sa : sb;
                t8[j] = keep + __shfl_xor_sync(FULL, send, 1);
            }
            float t4[4];
            #pragma unroll
            for (int j = 0; j < 4; j++) {
                float keep = x1 ? t8[2*j + 1] : t8[2*j];
                float send = x1 ? t8[2*j]     : t8[2*j + 1];
                t4[j] = keep + __shfl_xor_sync(FULL, send, 2);
            }
            float t2[2];
            #pragma unroll
            for (int j = 0; j < 2; j++) {
                float keep = x2 ? t4[2*j + 1] : t4[2*j];
                float send = x2 ? t4[2*j]     : t4[2*j + 1];
                t2[j] = keep + __shfl_xor_sync(FULL, send, 4);
            }
            {
                float keep = x3 ? t2[1] : t2[0];
                float send = x3 ? t2[0] : t2[1];
                float R = keep + __shfl_xor_sync(FULL, send, 8);
                float other = __shfl_xor_sync(FULL, R, 16);
                bq = fmaf(R, other, bq);
            }
        }
        GROUP_BAR(barid);   // group's conv_sh reads done before next row's conv overwrites
    }

    __syncthreads();   // realign all groups before conv_sh is repurposed

    // ---- epilogue: stage all 4 rows, conv_sh reused as os[row][hr*16+p], stride 65 ----
    #pragma unroll
    for (int hr = 0; hr < ROWS; hr++)
        #pragma unroll
        for (int tt = 0; tt < 4; tt++)
            conv_sh[((half*4 + tt)*32 + lane)*65 + hr*16 + p] = vr[hr*4 + tt];
    __syncthreads();

    // ---- coalesced writeout: 16 independent STG per thread ----
    {
        int x  = tid & 15;
        int hw = (tid >> 4) & 3;
        int r0 = tid >> 6;          // 0..15
        const float* os = conv_sh + hw*16 + x;
        float* ob = out + n*256*(HD*WD) + (hh0 + hw)*WD + w0 + x;
        #pragma unroll
        for (int k = 0; k < 16; k++) {
            int row = r0 + 16*k;
            ob[row*(HD*WD)] = os[row*65];
        }
    }
}

extern "C" void kernel_launch(void* const* d_in, const int* in_sizes, int n_in,
                              void* d_out, int out_size)
{
    const float* inp = (const float*)d_in[0];   // (4,4,32,96,96)
    const float* Wc  = (const float*)d_in[1];   // (4,5,5,1,8)
    const float* Wp  = (const float*)d_in[2];   // (4,16,8)
    const float* Wa  = (const float*)d_in[3];   // (4,16,8)
    const float* ba  = (const float*)d_in[4];   // (4,8)
    float* out = (float*)d_out;                 // (4,8,32,96,96)

    // weight prep (normalization/relayout/bias-fold) once
    prep_kernel<<<1, 512>>>(Wp, Wa, ba);

    const int smem_bytes = SMEM_F * (int)sizeof(float);
    cudaFuncSetAttribute(caps2d_fused_kernel,
                         cudaFuncAttributeMaxDynamicSharedMemorySize, smem_bytes);

    dim3 grid(WD / PXB, HD / ROWS, 4);   // (6, 24, 4)
    dim3 block(1024);
    caps2d_fused_kernel<<<grid, block, smem_bytes>>>(inp, Wc, out);
}